// round 3
// baseline (speedup 1.0000x reference)
#include <cuda_runtime.h>
#include <cuda_bf16.h>
#include <stdint.h>
#include <stddef.h>

#define CH 128
#define KTAPS 9
#define NMAX 400000

// ---------------- device scratch (allocation-free rule: __device__ globals) ----
__device__ __align__(256) __nv_bfloat16 g_fh[(NMAX + 1) * CH];   // feats hi (bf16), +1 zero row
__device__ __align__(256) __nv_bfloat16 g_fl[(NMAX + 1) * CH];   // feats lo (bf16)
__device__ __align__(256) __nv_bfloat16 g_wh[KTAPS * CH * CH];   // W^T hi: [k][cout][cin]
__device__ __align__(256) __nv_bfloat16 g_wl[KTAPS * CH * CH];   // W^T lo
__device__ float g_sum[CH];
__device__ float g_sum2[CH];
__device__ float g_scale[CH];
__device__ float g_shift[CH];

// ---------------- ptx helpers (compute_103-safe only!) -----------------------
__device__ __forceinline__ uint32_t smem_u32(const void* p) {
    uint32_t a;
    asm("{ .reg .u64 t; cvta.to.shared.u64 t, %1; cvt.u32.u64 %0, t; }" : "=r"(a) : "l"(p));
    return a;
}
__device__ __forceinline__ void cp16(uint32_t dst, const void* src) {
    asm volatile("cp.async.cg.shared.global [%0], [%1], 16;" :: "r"(dst), "l"(src) : "memory");
}
__device__ __forceinline__ void ldsm4(uint32_t* r, uint32_t addr) {
    asm volatile("ldmatrix.sync.aligned.m8n8.x4.shared.b16 {%0,%1,%2,%3}, [%4];"
                 : "=r"(r[0]), "=r"(r[1]), "=r"(r[2]), "=r"(r[3]) : "r"(addr));
}
__device__ __forceinline__ void mma_bf16(float* c, const uint32_t* a, uint32_t b0, uint32_t b1) {
    asm volatile(
        "mma.sync.aligned.m16n8k16.row.col.f32.bf16.bf16.f32 "
        "{%0,%1,%2,%3}, {%4,%5,%6,%7}, {%8,%9}, {%0,%1,%2,%3};"
        : "+f"(c[0]), "+f"(c[1]), "+f"(c[2]), "+f"(c[3])
        : "r"(a[0]), "r"(a[1]), "r"(a[2]), "r"(a[3]), "r"(b0), "r"(b1));
}

// ---------------- pre-kernels ------------------------------------------------
__global__ void zero_stats_kernel() {
    int c = threadIdx.x;
    g_sum[c] = 0.f;
    g_sum2[c] = 0.f;
}

// split feats into bf16 hi/lo; row N is the zero sentinel row
__global__ void split_feats_kernel(const float* __restrict__ f, int N) {
    long long i = (long long)blockIdx.x * 256 + threadIdx.x;  // one float4 per thread
    long long total4 = (long long)(N + 1) * (CH / 4);
    if (i >= total4) return;
    float4 v = make_float4(0.f, 0.f, 0.f, 0.f);
    if (i < (long long)N * (CH / 4)) v = reinterpret_cast<const float4*>(f)[i];
    float xs[4] = {v.x, v.y, v.z, v.w};
    __nv_bfloat16 hs[4], ls[4];
#pragma unroll
    for (int j = 0; j < 4; ++j) {
        __nv_bfloat16 h = __float2bfloat16(xs[j]);
        hs[j] = h;
        ls[j] = __float2bfloat16(xs[j] - __bfloat162float(h));
    }
    __nv_bfloat162* dh = reinterpret_cast<__nv_bfloat162*>(g_fh) + i * 2;
    __nv_bfloat162* dl = reinterpret_cast<__nv_bfloat162*>(g_fl) + i * 2;
    dh[0] = __halves2bfloat162(hs[0], hs[1]);
    dh[1] = __halves2bfloat162(hs[2], hs[3]);
    dl[0] = __halves2bfloat162(ls[0], ls[1]);
    dl[1] = __halves2bfloat162(ls[2], ls[3]);
}

// split + transpose W[k][cin][cout] -> Wt[k][cout][cin] hi/lo bf16
__global__ void split_w_kernel(const float* __restrict__ W) {
    int i = blockIdx.x * 256 + threadIdx.x;
    if (i >= KTAPS * CH * CH) return;
    int k = i >> 14;
    int rc = i & 16383;
    int cin = rc >> 7;
    int cout = rc & 127;
    float v = W[i];
    __nv_bfloat16 h = __float2bfloat16(v);
    __nv_bfloat16 l = __float2bfloat16(v - __bfloat162float(h));
    int o = (k << 14) + (cout << 7) + cin;
    g_wh[o] = h;
    g_wl[o] = l;
}

// ---------------- main conv kernel (mma.sync bf16, split 3-product) ----------
// smem tile: 128 rows x 64 cin (bf16) with 144B row pitch (128B data + 16B pad)
#define PITCH   144
#define TILE_B  (128 * PITCH)        // 18432 B
#define STAGE_B (4 * TILE_B)         // Ah, Al, Bh, Bl = 73728 B
#define TOFF    6144
#define SMEM_CONV (TOFF + 2 * STAGE_B)  // 153600 B

__device__ __forceinline__ uint32_t ldsm_addr(uint32_t tile, int rowbase, int ks, int lane) {
    // lanes 0-7: rows 0-7 koff 0 | 8-15: rows 8-15 koff 0 | 16-23: rows 0-7 koff 16B | 24-31: rows 8-15 koff 16B
    return tile + (uint32_t)((rowbase + (lane & 15)) * PITCH + ks * 32 + ((lane >> 4) << 4));
}

__global__ void __launch_bounds__(256, 1)
conv_kernel(const int* __restrict__ neigh, const float* __restrict__ bias,
            float* __restrict__ out) {
    extern __shared__ char smem[];
    const uint32_t sb = smem_u32(smem);
    const int tid = threadIdx.x;
    const int wid = tid >> 5;
    const int lane = tid & 31;
    const int m0 = blockIdx.x << 7;
    const int mwarp = wid & 3;    // 4 m-groups of 32 rows
    const int nwarp = wid >> 2;   // 2 n-groups of 64 couts

    int*   nb    = (int*)(smem + 64);      // [tap][row] neighbor indices, 1152 ints
    float* sbias = (float*)(smem + 4736);  // 128 floats

    for (int j = tid; j < KTAPS * 128; j += 256) {
        int r = j / KTAPS;
        int t = j - r * KTAPS;
        nb[t * 128 + r] = neigh[(size_t)(m0 + r) * KTAPS + t];
    }
    if (tid < 128) sbias[tid] = bias[tid];
    __syncthreads();

    float acc[2][8][4];
#pragma unroll
    for (int mt = 0; mt < 2; ++mt)
#pragma unroll
        for (int nt = 0; nt < 8; ++nt)
#pragma unroll
            for (int q = 0; q < 4; ++q) acc[mt][nt][q] = 0.f;

    // --- stage loader: tap = s>>1, chunk(64 cin) = s&1, buffer = s&1 of 2 ---
    auto load_stage = [&](int s) {
        const int tap = s >> 1;
        const int chunk = s & 1;
        const uint32_t tdst = sb + TOFF + (uint32_t)((s & 1) * STAGE_B);
        const char* whp = (const char*)g_wh + (tap << 15) + (chunk << 7);
        const char* wlp = (const char*)g_wl + (tap << 15) + (chunk << 7);
#pragma unroll
        for (int j = 0; j < 18; ++j) {    // 4608 cp16 across 256 threads
            int slot = (j << 8) + tid;
            int tile = slot / 1152;       // 0=Ah 1=Al 2=Bh 3=Bl
            int rem = slot - tile * 1152;
            int row = rem / 9;
            int seg = rem - row * 9;
            int sg = (seg < 8) ? seg : 0; // seg 8 = pad, load harmless dup
            const char* src;
            if (tile < 2) {
                int g = nb[(tap << 7) + row];
                const char* bp = (tile == 0) ? (const char*)g_fh : (const char*)g_fl;
                src = bp + ((size_t)g << 8) + (chunk << 7) + (sg << 4);
            } else {
                const char* bp = (tile == 2) ? whp : wlp;
                src = bp + (row << 8) + (sg << 4);
            }
            cp16(tdst + (uint32_t)(tile * TILE_B + row * PITCH + seg * 16), src);
        }
        asm volatile("cp.async.commit_group;" ::: "memory");
    };

    load_stage(0);
    load_stage(1);

#pragma unroll 1
    for (int s = 0; s < 18; ++s) {
        if (s == 17) asm volatile("cp.async.wait_group 0;" ::: "memory");
        else         asm volatile("cp.async.wait_group 1;" ::: "memory");
        __syncthreads();

        const uint32_t tb = sb + TOFF + (uint32_t)((s & 1) * STAGE_B);
        const uint32_t tAh = tb, tAl = tb + TILE_B, tBh = tb + 2 * TILE_B, tBl = tb + 3 * TILE_B;

#pragma unroll
        for (int ks = 0; ks < 4; ++ks) {   // 4 x k16 within the 64-cin chunk
            uint32_t ah[2][4], al[2][4], bh[4][4], bl[4][4];
#pragma unroll
            for (int mt = 0; mt < 2; ++mt) {
                int rb = mwarp * 32 + mt * 16;
                ldsm4(ah[mt], ldsm_addr(tAh, rb, ks, lane));
                ldsm4(al[mt], ldsm_addr(tAl, rb, ks, lane));
            }
#pragma unroll
            for (int p = 0; p < 4; ++p) {  // each x4 covers 16 couts (2 n-tiles)
                int rb = nwarp * 64 + p * 16;
                ldsm4(bh[p], ldsm_addr(tBh, rb, ks, lane));
                ldsm4(bl[p], ldsm_addr(tBl, rb, ks, lane));
            }
#pragma unroll
            for (int mt = 0; mt < 2; ++mt)
#pragma unroll
                for (int nt = 0; nt < 8; ++nt) {
                    int p = nt >> 1, od = nt & 1;
                    mma_bf16(acc[mt][nt], ah[mt], bh[p][od], bh[p][2 + od]);  // Ah*Bh
                    mma_bf16(acc[mt][nt], ah[mt], bl[p][od], bl[p][2 + od]);  // Ah*Bl
                    mma_bf16(acc[mt][nt], al[mt], bh[p][od], bh[p][2 + od]);  // Al*Bh
                }
        }
        if (s + 2 < 18) {
            __syncthreads();               // all warps done with buffer (s&1)
            load_stage(s + 2);
        }
    }

    // epilogue: bias add + store
#pragma unroll
    for (int mt = 0; mt < 2; ++mt) {
        int r0 = m0 + mwarp * 32 + mt * 16 + (lane >> 2);
#pragma unroll
        for (int nt = 0; nt < 8; ++nt) {
            int c = nwarp * 64 + nt * 8 + (lane & 3) * 2;
            float2 v0, v1;
            v0.x = acc[mt][nt][0] + sbias[c];
            v0.y = acc[mt][nt][1] + sbias[c + 1];
            v1.x = acc[mt][nt][2] + sbias[c];
            v1.y = acc[mt][nt][3] + sbias[c + 1];
            *reinterpret_cast<float2*>(out + (size_t)r0 * CH + c) = v0;
            *reinterpret_cast<float2*>(out + (size_t)(r0 + 8) * CH + c) = v1;
        }
    }
}

// ---------------- BN kernels -------------------------------------------------
__global__ void stats_kernel(const float* __restrict__ out, int N) {
    int c = threadIdx.x;  // 128 threads: channel
    float s = 0.f, s2 = 0.f;
    for (int r = blockIdx.x; r < N; r += gridDim.x) {
        float v = out[(size_t)r * CH + c];
        s += v;
        s2 += v * v;
    }
    atomicAdd(&g_sum[c], s);
    atomicAdd(&g_sum2[c], s2);
}

__global__ void finalize_kernel(const float* __restrict__ gamma, const float* __restrict__ beta, int N) {
    int c = threadIdx.x;
    float inv_n = 1.0f / (float)N;
    float m = g_sum[c] * inv_n;
    float var = fmaxf(g_sum2[c] * inv_n - m * m, 0.f);
    float sc = gamma[c] * rsqrtf(var + 1e-4f);
    g_scale[c] = sc;
    g_shift[c] = beta[c] - m * sc;
}

__device__ __forceinline__ float bn_lrelu(float v, int c) {
    float y = v * g_scale[c] + g_shift[c];
    return (y > 0.f) ? y : 0.333f * y;
}

__global__ void apply_kernel(float* __restrict__ out, long long n4) {
    long long i = (long long)blockIdx.x * 256 + threadIdx.x;
    if (i >= n4) return;
    float4 v = reinterpret_cast<const float4*>(out)[i];
    int c0 = (int)((i * 4) & (CH - 1));
    float4 rr;
    rr.x = bn_lrelu(v.x, c0 + 0);
    rr.y = bn_lrelu(v.y, c0 + 1);
    rr.z = bn_lrelu(v.z, c0 + 2);
    rr.w = bn_lrelu(v.w, c0 + 3);
    reinterpret_cast<float4*>(out)[i] = rr;
}

// ---------------- launch -----------------------------------------------------
extern "C" void kernel_launch(void* const* d_in, const int* in_sizes, int n_in,
                              void* d_out, int out_size) {
    const float* feats = (const float*)d_in[0];
    const float* W     = (const float*)d_in[1];
    const float* bias  = (const float*)d_in[2];
    const float* gamma = (const float*)d_in[3];
    const float* beta  = (const float*)d_in[4];
    const int*   neigh = (const int*)d_in[5];
    float* out = (float*)d_out;
    const int N = in_sizes[0] / CH;  // 400000

    cudaFuncSetAttribute(conv_kernel, cudaFuncAttributeMaxDynamicSharedMemorySize, SMEM_CONV);

    zero_stats_kernel<<<1, CH>>>();
    {
        long long t4 = (long long)(N + 1) * (CH / 4);
        split_feats_kernel<<<(unsigned)((t4 + 255) / 256), 256>>>(feats, N);
    }
    split_w_kernel<<<(KTAPS * CH * CH + 255) / 256, 256>>>(W);
    conv_kernel<<<N / 128, 256, SMEM_CONV>>>(neigh, bias, out);
    stats_kernel<<<1024, CH>>>(out, N);
    finalize_kernel<<<1, CH>>>(gamma, beta, N);
    {
        long long n4 = (long long)N * (CH / 4);
        apply_kernel<<<(unsigned)((n4 + 255) / 256), 256>>>(out, n4);
    }
}